// round 8
// baseline (speedup 1.0000x reference)
#include <cuda_runtime.h>
#include <cuda_bf16.h>
#include <cstdint>
#include <math.h>

#define N_NODES 200000
#define N_EDGES 800000
#define N_GRAPHS 4096
#define IN_FEAT 64
#define CAT_W 1024
#define N_TILES 1569            // max node tiles of 128 incl. bucket padding
#define PERM_SZ (N_TILES * 128)

// ---------------- device scratch (statically allocated; no cudaMalloc) ------
__device__ int   g_deg[N_NODES];
__device__ int   g_cnt[8];
__device__ int   g_cur[8];
__device__ int   g_pad_off[8];
__device__ int   g_perm[PERM_SZ];
__device__ int   g_eoff[N_NODES + 1];
__device__ int   g_ecur[N_NODES];
__device__ int   g_esrc[N_EDGES];
__device__ int   g_goff[N_GRAPHS + 1];
__device__ float g_msg[(size_t)N_NODES * 256];
__device__ float g_cat[(size_t)N_NODES * CAT_W];    // h0@0, h1@128, h2@256, h3@512
__device__ float g_pool[(size_t)N_GRAPHS * 256];

// ---------------- small prep kernels ---------------------------------------
__global__ void deg_kernel(const int* __restrict__ dst) {
    int e = blockIdx.x * blockDim.x + threadIdx.x;
    if (e < N_EDGES) atomicAdd(&g_deg[dst[e]], 1);
}

// block-local histogram -> one global atomic per bucket per block
__global__ void count_kernel() {
    __shared__ int h[6];
    if (threadIdx.x < 6) h[threadIdx.x] = 0;
    __syncthreads();
    int i = blockIdx.x * blockDim.x + threadIdx.x;
    if (i < N_NODES) atomicAdd(&h[min(g_deg[i], 5)], 1);
    __syncthreads();
    if (threadIdx.x < 6 && h[threadIdx.x]) atomicAdd(&g_cnt[threadIdx.x], h[threadIdx.x]);
}

__global__ void scan_kernel() {
    if (threadIdx.x == 0 && blockIdx.x == 0) {
        int off = 0;
        for (int b = 0; b < 6; b++) {
            g_pad_off[b] = off;
            off += ((g_cnt[b] + 127) >> 7) << 7;   // pad each bucket to 128
        }
        g_pad_off[6] = off;
    }
}

// block-local ranks: one global atomic per bucket per block
__global__ void scatter_kernel() {
    __shared__ int h[6], base[6];
    if (threadIdx.x < 6) h[threadIdx.x] = 0;
    __syncthreads();
    int i = blockIdx.x * blockDim.x + threadIdx.x;
    int b = -1, r = 0;
    if (i < N_NODES) {
        b = min(g_deg[i], 5);
        r = atomicAdd(&h[b], 1);
    }
    __syncthreads();
    if (threadIdx.x < 6 && h[threadIdx.x]) base[threadIdx.x] = atomicAdd(&g_cur[threadIdx.x], h[threadIdx.x]);
    __syncthreads();
    if (b >= 0) g_perm[g_pad_off[b] + base[b] + r] = i;
}

// exclusive scan of g_deg -> g_eoff  (single block, 1024 threads)
__global__ void scan_deg_kernel() {
    __shared__ int part[1024];
    const int tid = threadIdx.x;
    const int chunk = (N_NODES + 1023) / 1024;
    int s0 = tid * chunk;
    int s1 = min(s0 + chunk, N_NODES);
    int s = 0;
    for (int i = s0; i < s1; i++) s += g_deg[i];
    part[tid] = s;
    __syncthreads();
    for (int off = 1; off < 1024; off <<= 1) {
        int v = (tid >= off) ? part[tid - off] : 0;
        __syncthreads();
        part[tid] += v;
        __syncthreads();
    }
    int base = (tid == 0) ? 0 : part[tid - 1];
    for (int i = s0; i < s1; i++) {
        g_eoff[i] = base;
        base += g_deg[i];
    }
    if (tid == 1023) g_eoff[N_NODES] = N_EDGES;
}

__global__ void csr_scatter_kernel(const int* __restrict__ src, const int* __restrict__ dst) {
    int e = blockIdx.x * blockDim.x + threadIdx.x;
    if (e >= N_EDGES) return;
    int d = dst[e];
    int pos = atomicAdd(&g_ecur[d], 1);
    g_esrc[g_eoff[d] + pos] = src[e];
}

// graph boundaries from sorted batch
__global__ void goff_kernel(const int* __restrict__ batch) {
    int i = blockIdx.x * blockDim.x + threadIdx.x;
    if (i >= N_NODES) return;
    int bc = batch[i];
    if (i == 0) {
        for (int g = 0; g <= bc; g++) g_goff[g] = 0;
    } else {
        int bp = batch[i - 1];
        for (int g = bp + 1; g <= bc; g++) g_goff[g] = i;
    }
    if (i == N_NODES - 1) {
        for (int g = bc + 1; g <= N_GRAPHS; g++) g_goff[g] = N_NODES;
    }
}

// ---------------- CSR neighbor-sum aggregation ------------------------------
template <int C4>  // C4 = c_in/4
__global__ void agg_csr_kernel(const float* __restrict__ in, int in_stride) {
    int idx = blockIdx.x * blockDim.x + threadIdx.x;
    if (idx >= N_NODES * C4) return;
    int node = idx / C4;
    int c = (idx % C4) * 4;
    int e0 = g_eoff[node], e1 = g_eoff[node + 1];
    float4 acc = make_float4(0.f, 0.f, 0.f, 0.f);
    for (int e = e0; e < e1; e++) {
        int s = g_esrc[e];
        float4 v = *(const float4*)(in + (size_t)s * in_stride + c);
        acc.x += v.x; acc.y += v.y; acc.z += v.z; acc.w += v.w;
    }
    *(float4*)(g_msg + (size_t)node * (C4 * 4) + c) = acc;
}

// ---------------- tf32 tensor-core helpers ----------------------------------
__device__ __forceinline__ uint32_t f2tf(float f) {
    uint32_t u;
    asm("cvt.rna.tf32.f32 %0, %1;" : "=r"(u) : "f"(f));
    return u;
}

__device__ __forceinline__ void split_tf32(float v, uint32_t& hi, uint32_t& lo) {
    hi = f2tf(v);
    lo = f2tf(v - __uint_as_float(hi));
}

__device__ __forceinline__ void mma_tf32(float* c, const uint32_t* a, const uint32_t* b) {
    asm volatile(
        "mma.sync.aligned.m16n8k8.row.col.f32.tf32.tf32.f32 "
        "{%0,%1,%2,%3}, {%4,%5,%6,%7}, {%8,%9}, {%0,%1,%2,%3};"
        : "+f"(c[0]), "+f"(c[1]), "+f"(c[2]), "+f"(c[3])
        : "r"(a[0]), "r"(a[1]), "r"(a[2]), "r"(a[3]), "r"(b[0]), "r"(b[1]));
}

// ---------------- bucketed grouped GEMM (3xTF32, double-buffered smem) ------
// dynamic smem: 4 arrays x 2 buffers x [16][136] u32 = 69632 bytes
#define TW (16 * 136)
#define SMEM_GEMM_BYTES (8 * TW * 4)

template <int CIN, int COUT>
__launch_bounds__(256, 2)
__global__ void gemm_kernel(const float* __restrict__ in, int in_stride,
                            float* __restrict__ out,
                            const float* __restrict__ Wl,
                            const float* __restrict__ bl,
                            const float* __restrict__ Wr) {
    constexpr int K = 2 * CIN;
    constexpr int NCH = K / 16;
    extern __shared__ uint32_t dsm[];
    uint32_t* AsH = dsm;               // [2][16][136]
    uint32_t* AsL = dsm + 2 * TW;
    uint32_t* BsH = dsm + 4 * TW;
    uint32_t* BsL = dsm + 6 * TW;

    const int row0 = blockIdx.x * 128;
    if (row0 >= g_pad_off[6]) return;

    int d = 0;
    #pragma unroll
    for (int b = 1; b < 6; b++)
        if (row0 >= g_pad_off[b]) d = b;

    const int ocol0 = blockIdx.y * 128;
    const int t = threadIdx.x;
    const int lane = t & 31;
    const int warp = t >> 5;
    const int wm = (warp >> 2) * 64;
    const int wn = (warp & 3) * 32;
    const int lq = lane & 3;
    const int lg = lane >> 2;

    const int arow = t >> 1, akb = (t & 1) * 8;
    const int anode = g_perm[row0 + arow];
    const int bk = t >> 4, bob = (t & 15) * 8;

    const float* WlB = Wl + (size_t)d * CIN * COUT;
    const float* WrB = Wr + (size_t)d * CIN * COUT;

    float acc[4][4][4];
    #pragma unroll
    for (int mt = 0; mt < 4; mt++)
        #pragma unroll
        for (int nt = 0; nt < 4; nt++)
            #pragma unroll
            for (int i = 0; i < 4; i++) acc[mt][nt][i] = 0.f;

    float ar[8], br[8];

    auto load_regs = [&](int k0) {
        int ka = k0 + akb;
        if (anode >= 0) {
            const float* s = (ka < CIN) ? (g_msg + (size_t)anode * CIN + ka)
                                        : (in + (size_t)anode * in_stride + (ka - CIN));
            *(float4*)&ar[0] = *(const float4*)s;
            *(float4*)&ar[4] = *(const float4*)(s + 4);
        } else {
            #pragma unroll
            for (int i = 0; i < 8; i++) ar[i] = 0.f;
        }
        int kb = k0 + bk;
        const float* w = (kb < CIN) ? (WlB + (size_t)kb * COUT + ocol0 + bob)
                                    : (WrB + (size_t)(kb - CIN) * COUT + ocol0 + bob);
        *(float4*)&br[0] = *(const float4*)w;
        *(float4*)&br[4] = *(const float4*)(w + 4);
    };

    auto store_smem = [&](int buf) {
        uint32_t* aH = AsH + buf * TW;
        uint32_t* aL = AsL + buf * TW;
        uint32_t* bH = BsH + buf * TW;
        uint32_t* bL = BsL + buf * TW;
        #pragma unroll
        for (int i = 0; i < 8; i++) {
            uint32_t h, l;
            split_tf32(ar[i], h, l);
            aH[(akb + i) * 136 + arow] = h;
            aL[(akb + i) * 136 + arow] = l;
        }
        uint4 h0, h1, l0, l1;
        split_tf32(br[0], h0.x, l0.x); split_tf32(br[1], h0.y, l0.y);
        split_tf32(br[2], h0.z, l0.z); split_tf32(br[3], h0.w, l0.w);
        split_tf32(br[4], h1.x, l1.x); split_tf32(br[5], h1.y, l1.y);
        split_tf32(br[6], h1.z, l1.z); split_tf32(br[7], h1.w, l1.w);
        *(uint4*)&bH[bk * 136 + bob]     = h0;
        *(uint4*)&bH[bk * 136 + bob + 4] = h1;
        *(uint4*)&bL[bk * 136 + bob]     = l0;
        *(uint4*)&bL[bk * 136 + bob + 4] = l1;
    };

    load_regs(0);
    store_smem(0);

    for (int ch = 0; ch < NCH; ch++) {
        __syncthreads();   // buf(ch) fully stored; buf(ch^1) fully consumed
        const int buf = ch & 1;
        if (ch + 1 < NCH) load_regs((ch + 1) * 16);   // LDG latency hidden by MMAs

        const uint32_t* aH = AsH + buf * TW;
        const uint32_t* aL = AsL + buf * TW;
        const uint32_t* bH = BsH + buf * TW;
        const uint32_t* bL = BsL + buf * TW;

        #pragma unroll
        for (int ks = 0; ks < 16; ks += 8) {
            uint32_t bh[4][2], blo[4][2];
            #pragma unroll
            for (int nt = 0; nt < 4; nt++) {
                int cb = wn + nt * 8 + lg;
                bh[nt][0]  = bH[(ks + lq) * 136 + cb];
                bh[nt][1]  = bH[(ks + lq + 4) * 136 + cb];
                blo[nt][0] = bL[(ks + lq) * 136 + cb];
                blo[nt][1] = bL[(ks + lq + 4) * 136 + cb];
            }
            #pragma unroll
            for (int mt = 0; mt < 4; mt++) {
                int rb = wm + mt * 16 + lg;
                uint32_t ah[4], al[4];
                ah[0] = aH[(ks + lq) * 136 + rb];     ah[1] = aH[(ks + lq) * 136 + rb + 8];
                ah[2] = aH[(ks + lq + 4) * 136 + rb]; ah[3] = aH[(ks + lq + 4) * 136 + rb + 8];
                al[0] = aL[(ks + lq) * 136 + rb];     al[1] = aL[(ks + lq) * 136 + rb + 8];
                al[2] = aL[(ks + lq + 4) * 136 + rb]; al[3] = aL[(ks + lq + 4) * 136 + rb + 8];
                #pragma unroll
                for (int nt = 0; nt < 4; nt++) {
                    mma_tf32(acc[mt][nt], ah, blo[nt]);
                    mma_tf32(acc[mt][nt], al, bh[nt]);
                    mma_tf32(acc[mt][nt], ah, bh[nt]);
                }
            }
        }

        if (ch + 1 < NCH) store_smem(buf ^ 1);   // safe: all threads passed this iter's sync
    }

    #pragma unroll
    for (int mt = 0; mt < 4; mt++) {
        int r0 = row0 + wm + mt * 16 + lg;
        int n0 = g_perm[r0];
        int n1 = g_perm[r0 + 8];
        #pragma unroll
        for (int nt = 0; nt < 4; nt++) {
            int col = wn + nt * 8 + 2 * lq;
            float b0 = bl[(size_t)d * COUT + ocol0 + col];
            float b1 = bl[(size_t)d * COUT + ocol0 + col + 1];
            if (n0 >= 0) {
                float2 v = make_float2(acc[mt][nt][0] + b0, acc[mt][nt][1] + b1);
                *(float2*)(out + (size_t)n0 * CAT_W + ocol0 + col) = v;
            }
            if (n1 >= 0) {
                float2 v = make_float2(acc[mt][nt][2] + b0, acc[mt][nt][3] + b1);
                *(float2*)(out + (size_t)n1 * CAT_W + ocol0 + col) = v;
            }
        }
    }
}

// ---------------- segmented global add pool of h3 over batch -----------------
__global__ void pool_seg_kernel() {
    int idx = blockIdx.x * blockDim.x + threadIdx.x;
    if (idx >= N_GRAPHS * 64) return;
    int g = idx >> 6;
    int c = (idx & 63) * 4;
    int i0 = g_goff[g], i1 = g_goff[g + 1];
    float4 acc = make_float4(0.f, 0.f, 0.f, 0.f);
    for (int i = i0; i < i1; i++) {
        float4 v = *(const float4*)(g_cat + (size_t)i * CAT_W + 512 + c);
        acc.x += v.x; acc.y += v.y; acc.z += v.z; acc.w += v.w;
    }
    *(float4*)(g_pool + (size_t)g * 256 + c) = acc;
}

// ---------------- final linear (1024 -> 2) + softmax -------------------------
__launch_bounds__(256)
__global__ void final_kernel(const float* __restrict__ Wf, const float* __restrict__ bf,
                             const int* __restrict__ batch, float* __restrict__ out) {
    __shared__ float wf_s[CAT_W * 2];
    for (int i = threadIdx.x; i < CAT_W * 2; i += 256) wf_s[i] = Wf[i];
    __syncthreads();

    int warp = threadIdx.x >> 5, lane = threadIdx.x & 31;
    int node = blockIdx.x * 8 + warp;
    if (node >= N_NODES) return;

    const float* row = g_cat + (size_t)node * CAT_W;
    const float* prow = g_pool + (size_t)batch[node] * 256;

    float s0 = 0.f, s1 = 0.f;
    #pragma unroll
    for (int j = 0; j < 24; j++) {
        int c = j * 32 + lane;
        float v = row[c];
        s0 += v * wf_s[2 * c];
        s1 += v * wf_s[2 * c + 1];
    }
    #pragma unroll
    for (int j = 0; j < 8; j++) {
        int c = j * 32 + lane;
        float v = prow[c];
        int cc = 768 + c;
        s0 += v * wf_s[2 * cc];
        s1 += v * wf_s[2 * cc + 1];
    }
    #pragma unroll
    for (int off = 16; off; off >>= 1) {
        s0 += __shfl_down_sync(0xFFFFFFFFu, s0, off);
        s1 += __shfl_down_sync(0xFFFFFFFFu, s1, off);
    }
    if (lane == 0) {
        float l0 = s0 + bf[0], l1 = s1 + bf[1];
        float m = fmaxf(l0, l1);
        float e0 = expf(l0 - m), e1 = expf(l1 - m);
        float inv = 1.f / (e0 + e1);
        out[(size_t)node * 2 + 0] = e0 * inv;
        out[(size_t)node * 2 + 1] = e1 * inv;
    }
}

// ---------------- host orchestration ----------------------------------------
extern "C" void kernel_launch(void* const* d_in, const int* in_sizes, int n_in,
                              void* d_out, int out_size) {
    const float* x     = (const float*)d_in[0];
    const int*   ei    = (const int*)d_in[1];
    const int*   batch = (const int*)d_in[2];
    const float* Wl[4] = {(const float*)d_in[3], (const float*)d_in[6], (const float*)d_in[9],  (const float*)d_in[12]};
    const float* bl[4] = {(const float*)d_in[4], (const float*)d_in[7], (const float*)d_in[10], (const float*)d_in[13]};
    const float* Wr[4] = {(const float*)d_in[5], (const float*)d_in[8], (const float*)d_in[11], (const float*)d_in[14]};
    const float* Wf = (const float*)d_in[15];
    const float* bf = (const float*)d_in[16];
    float* out = (float*)d_out;

    const int* src = ei;
    const int* dst = ei + N_EDGES;

    // raise dynamic smem limit for the GEMM instantiations (idempotent)
    cudaFuncSetAttribute(gemm_kernel<64, 128>,  cudaFuncAttributeMaxDynamicSharedMemorySize, SMEM_GEMM_BYTES);
    cudaFuncSetAttribute(gemm_kernel<128, 128>, cudaFuncAttributeMaxDynamicSharedMemorySize, SMEM_GEMM_BYTES);
    cudaFuncSetAttribute(gemm_kernel<128, 256>, cudaFuncAttributeMaxDynamicSharedMemorySize, SMEM_GEMM_BYTES);
    cudaFuncSetAttribute(gemm_kernel<256, 256>, cudaFuncAttributeMaxDynamicSharedMemorySize, SMEM_GEMM_BYTES);

    void *p_deg, *p_cnt, *p_cur, *p_perm, *p_ecur, *p_cat;
    cudaGetSymbolAddress(&p_deg, g_deg);
    cudaGetSymbolAddress(&p_cnt, g_cnt);
    cudaGetSymbolAddress(&p_cur, g_cur);
    cudaGetSymbolAddress(&p_perm, g_perm);
    cudaGetSymbolAddress(&p_ecur, g_ecur);
    cudaGetSymbolAddress(&p_cat, g_cat);

    float* cat = (float*)p_cat;

    // ---- degree + bucketed permutation + CSR + graph offsets
    cudaMemsetAsync(p_deg, 0, N_NODES * sizeof(int));
    cudaMemsetAsync(p_cnt, 0, 8 * sizeof(int));
    cudaMemsetAsync(p_cur, 0, 8 * sizeof(int));
    cudaMemsetAsync(p_ecur, 0, N_NODES * sizeof(int));
    cudaMemsetAsync(p_perm, 0xFF, PERM_SZ * sizeof(int));   // -1 everywhere

    deg_kernel<<<(N_EDGES + 255) / 256, 256>>>(dst);
    count_kernel<<<(N_NODES + 255) / 256, 256>>>();
    scan_kernel<<<1, 32>>>();
    scatter_kernel<<<(N_NODES + 255) / 256, 256>>>();
    scan_deg_kernel<<<1, 1024>>>();
    csr_scatter_kernel<<<(N_EDGES + 255) / 256, 256>>>(src, dst);
    goff_kernel<<<(N_NODES + 255) / 256, 256>>>(batch);

    // ---- layer 0: c_in=64 (input x) -> c_out=128 at cat col 0
    agg_csr_kernel<16><<<(N_NODES * 16 + 255) / 256, 256>>>(x, IN_FEAT);
    gemm_kernel<64, 128><<<dim3(N_TILES, 1), 256, SMEM_GEMM_BYTES>>>(x, IN_FEAT, cat + 0, Wl[0], bl[0], Wr[0]);

    // ---- layer 1: c_in=128 (cat col 0) -> c_out=128 at cat col 128
    agg_csr_kernel<32><<<(N_NODES * 32 + 255) / 256, 256>>>(cat + 0, CAT_W);
    gemm_kernel<128, 128><<<dim3(N_TILES, 1), 256, SMEM_GEMM_BYTES>>>(cat + 0, CAT_W, cat + 128, Wl[1], bl[1], Wr[1]);

    // ---- layer 2: c_in=128 (cat col 128) -> c_out=256 at cat col 256
    agg_csr_kernel<32><<<(N_NODES * 32 + 255) / 256, 256>>>(cat + 128, CAT_W);
    gemm_kernel<128, 256><<<dim3(N_TILES, 2), 256, SMEM_GEMM_BYTES>>>(cat + 128, CAT_W, cat + 256, Wl[2], bl[2], Wr[2]);

    // ---- layer 3: c_in=256 (cat col 256) -> c_out=256 at cat col 512
    agg_csr_kernel<64><<<(N_NODES * 64 + 255) / 256, 256>>>(cat + 256, CAT_W);
    gemm_kernel<256, 256><<<dim3(N_TILES, 2), 256, SMEM_GEMM_BYTES>>>(cat + 256, CAT_W, cat + 512, Wl[3], bl[3], Wr[3]);

    // ---- segmented pool of h3, then final linear + softmax
    pool_seg_kernel<<<(N_GRAPHS * 64 + 255) / 256, 256>>>();
    final_kernel<<<N_NODES / 8, 256>>>(Wf, bf, batch, out);
}